// round 16
// baseline (speedup 1.0000x reference)
#include <cuda_runtime.h>
#include <cuda_fp16.h>
#include <cstdint>

#define B_ 4
#define C_ 128
#define N_ 4096

// ---------------------------------------------------------------------------
// Scratch (static device globals, 16B aligned via uint4). All fp16 payloads.
// ---------------------------------------------------------------------------
__device__ uint4 g_qt_hi[(size_t)B_*N_*C_/8];   // fp16 [b][n][c]
__device__ uint4 g_qt_lo[(size_t)B_*N_*C_/8];
__device__ uint4 g_kt_hi[(size_t)B_*N_*C_/8];   // fp16 [b][n][c]
__device__ uint4 g_kt_lo[(size_t)B_*N_*C_/8];
__device__ uint4 g_v   [(size_t)B_*N_*C_/8];    // fp16 [b][c][n]  (single)

// ---------------------------------------------------------------------------
// Portable tensor-core helpers (plain sm_103 target)
// ---------------------------------------------------------------------------
__device__ __forceinline__ uint32_t smem_u32(const void* p) {
    uint32_t a;
    asm("{ .reg .u64 t; cvta.to.shared.u64 t, %1; cvt.u32.u64 %0, t; }"
        : "=r"(a) : "l"(p));
    return a;
}
__device__ __forceinline__ void ldsm_x4(uint32_t* r, uint32_t addr) {
    asm volatile("ldmatrix.sync.aligned.m8n8.x4.shared.b16 {%0,%1,%2,%3}, [%4];"
                 : "=r"(r[0]), "=r"(r[1]), "=r"(r[2]), "=r"(r[3]) : "r"(addr));
}
__device__ __forceinline__ void ldsm_x4_t(uint32_t* r, uint32_t addr) {
    asm volatile("ldmatrix.sync.aligned.m8n8.x4.trans.shared.b16 {%0,%1,%2,%3}, [%4];"
                 : "=r"(r[0]), "=r"(r[1]), "=r"(r[2]), "=r"(r[3]) : "r"(addr));
}
__device__ __forceinline__ void mma16816(float* c, const uint32_t* a, const uint32_t* b) {
    asm volatile(
        "mma.sync.aligned.m16n8k16.row.col.f32.f16.f16.f32 "
        "{%0,%1,%2,%3}, {%4,%5,%6,%7}, {%8,%9}, {%0,%1,%2,%3};"
        : "+f"(c[0]), "+f"(c[1]), "+f"(c[2]), "+f"(c[3])
        : "r"(a[0]), "r"(a[1]), "r"(a[2]), "r"(a[3]), "r"(b[0]), "r"(b[1]));
}
__device__ __forceinline__ uint32_t packh(float a, float b) {   // low16 = a
    __half2 h = __floats2half2_rn(a, b);
    return *reinterpret_cast<uint32_t*>(&h);
}
__device__ __forceinline__ void split2h(float a, float b, uint32_t& h, uint32_t& l) {
    __half2 hh = __floats2half2_rn(a, b);
    float2  hf = __half22float2(hh);
    __half2 ll = __floats2half2_rn(a - hf.x, b - hf.y);
    h = *reinterpret_cast<uint32_t*>(&hh);
    l = *reinterpret_cast<uint32_t*>(&ll);
}

// Swizzled tiles: 256B rows (16 chunks), 64B rows (4 chunks)
__device__ __forceinline__ uint32_t sw_off(int r, int ch) {
    return (uint32_t)(r * 256 + ((ch ^ (r & 7)) << 4));
}
__device__ __forceinline__ uint32_t sw4(int r, int ch) {
    return (uint32_t)(r * 64 + ((ch ^ (r & 3)) << 4));
}
// Copy 128x(16 uint4) fp16 tile into swizzled SMEM (NT threads).
template <int NT>
__device__ __forceinline__ void stage_tile_n(char* dst, const uint4* __restrict__ g,
                                             int rs, int tid) {
    #pragma unroll
    for (int it = 0; it < 2048 / NT; it++) {
        int i = tid + it * NT;
        int r = i >> 4, ch = i & 15;
        uint4 v = g[(size_t)r * rs + ch];
        *(uint4*)(dst + sw_off(r, ch)) = v;
    }
}
// fp32 gmem tile (128x128, stride rs floats) -> swizzled fp16 hi/lo (512 thr)
__device__ __forceinline__ void stage_split512(char* hi, char* lo,
                                               const float* __restrict__ g,
                                               size_t rs, int tid) {
    #pragma unroll
    for (int it = 0; it < 4; it++) {
        int i = tid + it * 512;
        int r = i >> 4, ch = i & 15;
        const float* p = g + (size_t)r * rs + ch * 8;
        float4 f0 = *(const float4*)p;
        float4 f1 = *(const float4*)(p + 4);
        uint32_t h0,l0,h1,l1,h2,l2,h3,l3;
        split2h(f0.x, f0.y, h0, l0);
        split2h(f0.z, f0.w, h1, l1);
        split2h(f1.x, f1.y, h2, l2);
        split2h(f1.z, f1.w, h3, l3);
        uint32_t off = sw_off(r, ch);
        *(uint4*)(hi + off) = make_uint4(h0, h1, h2, h3);
        *(uint4*)(lo + off) = make_uint4(l0, l1, l2, l3);
    }
}
// fp32 gmem tile (128x128, stride rs floats) -> swizzled SINGLE fp16 (512 thr)
__device__ __forceinline__ void stage_half512(char* dst, const float* __restrict__ g,
                                              size_t rs, int tid) {
    #pragma unroll
    for (int it = 0; it < 4; it++) {
        int i = tid + it * 512;
        int r = i >> 4, ch = i & 15;
        const float* p = g + (size_t)r * rs + ch * 8;
        float4 f0 = *(const float4*)p;
        float4 f1 = *(const float4*)(p + 4);
        *(uint4*)(dst + sw_off(r, ch)) =
            make_uint4(packh(f0.x, f0.y), packh(f0.z, f0.w),
                       packh(f1.x, f1.y), packh(f1.z, f1.w));
    }
}

#define CP16(s, g) asm volatile("cp.async.cg.shared.global [%0], [%1], 16;" \
                                :: "r"(s), "l"(g) : "memory")
#define CP_COMMIT() asm volatile("cp.async.commit_group;" ::: "memory")
#define CP_WAIT1()  asm volatile("cp.async.wait_group 1;" ::: "memory")

// ---------------------------------------------------------------------------
// Kernel 1: merged QKV projection, 512 threads / 16 warps.
// Each warp: one 16-row strip x HALF the output dim (halved latency chain).
// ---------------------------------------------------------------------------
#define PJ_WHI 0
#define PJ_WLO 32768
#define PJ_XHI 65536
#define PJ_XLO 98304
#define PJ_TOTAL 131072

__global__ __launch_bounds__(512, 1) void proj_qkv_mma(
    const float* __restrict__ x,
    const float* __restrict__ Wq, const float* __restrict__ bq,
    const float* __restrict__ Wk, const float* __restrict__ bk,
    const float* __restrict__ Wv, const float* __restrict__ bv)
{
    extern __shared__ char smc[];
    const int tid = threadIdx.x, lane = tid & 31, wid = tid >> 5;
    const int nt0 = blockIdx.x, b = blockIdx.y;
    const int n0 = nt0 * 128;
    const uint32_t smb = smem_u32(smc);

    stage_split512(smc + PJ_XHI, smc + PJ_XLO, x + (size_t)b*C_*N_ + n0, N_, tid);

    for (int which = 0; which < 3; which++) {
        const float* W    = (which == 0) ? Wq : (which == 1) ? Wk : Wv;
        const float* bias = (which == 0) ? bq : (which == 1) ? bk : bv;
        if (which) __syncthreads();
        stage_split512(smc + PJ_WHI, smc + PJ_WLO, W, 128, tid);
        __syncthreads();

        float acc[8][4];
        #pragma unroll
        for (int i = 0; i < 8; i++)
            #pragma unroll
            for (int k = 0; k < 4; k++) acc[i][k] = 0.f;

        if (which < 2) {
            // C[n][o]: A = x^T (trans ldsm), B = W.  strip sn, o-half oh.
            const int sn = wid >> 1, oh = wid & 1;
            const int ta_r = (lane & 7) + ((lane >> 4) << 3);
            const int ta_c = (lane >> 3) & 1;
            const int br = (lane & 7) + ((lane >> 4) << 3);
            const int bc = (lane >> 3) & 1;
            const int nch = sn * 2;
            #pragma unroll
            for (int J = 0; J < 8; J++) {
                uint32_t axh[4], axl[4];
                ldsm_x4_t(axh, smb + PJ_XHI + sw_off(J*16 + ta_r, nch + ta_c));
                ldsm_x4_t(axl, smb + PJ_XLO + sw_off(J*16 + ta_r, nch + ta_c));
                #pragma unroll
                for (int ot = 0; ot < 4; ot++) {
                    uint32_t bwh[4], bwl[4];
                    ldsm_x4(bwh, smb + PJ_WHI + sw_off(oh*64 + ot*16 + br, 2*J + bc));
                    ldsm_x4(bwl, smb + PJ_WLO + sw_off(oh*64 + ot*16 + br, 2*J + bc));
                    mma16816(acc[2*ot],   axh, bwh);
                    mma16816(acc[2*ot+1], axh, bwh + 2);
                    mma16816(acc[2*ot],   axh, bwl);
                    mma16816(acc[2*ot+1], axh, bwl + 2);
                    mma16816(acc[2*ot],   axl, bwh);
                    mma16816(acc[2*ot+1], axl, bwh + 2);
                }
            }
            uint32_t* ohp = (uint32_t*)((which == 0) ? g_qt_hi : g_kt_hi);
            uint32_t* olp = (uint32_t*)((which == 0) ? g_qt_lo : g_kt_lo);
            const int n_g = n0 + sn*16 + (lane >> 2);
            #pragma unroll
            for (int ct = 0; ct < 8; ct++) {
                int o = oh*64 + ct*8 + (lane & 3)*2;
                float b0 = bias[o], b1 = bias[o+1];
                uint32_t h, l;
                size_t idx = ((size_t)b*N_ + n_g)*64 + oh*32 + ct*4 + (lane & 3);
                split2h(acc[ct][0] + b0, acc[ct][1] + b1, h, l);
                ohp[idx] = h; olp[idx] = l;
                split2h(acc[ct][2] + b0, acc[ct][3] + b1, h, l);
                ohp[idx + 8*64] = h; olp[idx + 8*64] = l;
            }
        } else {
            // C[o][n]: A = W, B = x^T (trans ldsm).  o-strip so, n-half nh.
            const int so = wid >> 1, nh = wid & 1;
            const int ar = (lane & 7) + (((lane >> 3) & 1) << 3);
            const int ac = lane >> 4;
            const int tb_r = (lane & 7) + (((lane >> 3) & 1) << 3);
            const int tb_c = lane >> 4;
            #pragma unroll
            for (int J = 0; J < 8; J++) {
                uint32_t awh[4], awl[4];
                ldsm_x4(awh, smb + PJ_WHI + sw_off(so*16 + ar, 2*J + ac));
                ldsm_x4(awl, smb + PJ_WLO + sw_off(so*16 + ar, 2*J + ac));
                #pragma unroll
                for (int nt = 0; nt < 4; nt++) {
                    uint32_t bxh[4], bxl[4];
                    ldsm_x4_t(bxh, smb + PJ_XHI + sw_off(J*16 + tb_r, nh*8 + nt*2 + tb_c));
                    ldsm_x4_t(bxl, smb + PJ_XLO + sw_off(J*16 + tb_r, nh*8 + nt*2 + tb_c));
                    mma16816(acc[2*nt],   awh, bxh);
                    mma16816(acc[2*nt+1], awh, bxh + 2);
                    mma16816(acc[2*nt],   awh, bxl);
                    mma16816(acc[2*nt+1], awh, bxl + 2);
                    mma16816(acc[2*nt],   awl, bxh);
                    mma16816(acc[2*nt+1], awl, bxh + 2);
                }
            }
            uint32_t* ov = (uint32_t*)g_v;
            const int o_g = so*16 + (lane >> 2);
            const float b0 = bias[o_g], b1 = bias[o_g + 8];
            #pragma unroll
            for (int nt = 0; nt < 8; nt++) {
                size_t idx = (((size_t)b*C_ + o_g)*N_ + n0)/2 + nh*32 + nt*4 + (lane & 3);
                ov[idx]            = packh(acc[nt][0] + b0, acc[nt][1] + b0);
                ov[idx + 8*(N_/2)] = packh(acc[nt][2] + b1, acc[nt][3] + b1);
            }
        }
    }
}

// ---------------------------------------------------------------------------
// Kernel 2: WARP-SPECIALIZED flash attention + fused output projection.
// 512 threads = 16 warps.  wid 8..15 = S warps (GEMM1 + softmax -> P smem),
// wid 0..7 = O warps (O-rescale + GEMM2; epilogue).  Strip = wid & 7.
// 32-key chunks, lag-1 pipeline: iter jt = S produces P[jt], O consumes
// P[jt-1] with V[jt-1].  One __syncthreads per iter.  S warps sit at high
// wid so the arbiter drains their MMAs first; softmax overlaps O's MMAs.
// ---------------------------------------------------------------------------
#define NCH 128
#define AT_QHI 0
#define AT_QLO 32768
#define KR 65536
#define KBUF_SZ 16384
#define VR 114688
#define VBUF_SZ 8192
#define PB 147456
#define PBUF_SZ 8192
#define AL 163840
#define LS 164864
#define AT_TOTAL 165888
// epilogue overlays (K/V/P regions free after mainloop)
#define EP_WO 65536
#define EP_YS 98304
#define YS_STR 132

__device__ __forceinline__ void stage_kv32(uint32_t smb, int b, int chunk, int tid) {
    const int j0 = chunk * 32;
    const uint32_t kb = smb + KR + (uint32_t)(chunk % 3) * KBUF_SZ;
    {
        int r = tid >> 4, ch = tid & 15;         // 32 key rows x 16 chunks
        uint32_t so = sw_off(r, ch);
        CP16(kb + so,        g_kt_hi + ((size_t)b*N_ + j0 + r)*16 + ch);
        CP16(kb + 8192 + so, g_kt_lo + ((size_t)b*N_ + j0 + r)*16 + ch);
    }
    const uint32_t vb = smb + VR + (uint32_t)(chunk % 4) * VBUF_SZ;
    {
        int r = tid >> 2, ch = tid & 3;          // 128 c rows x 4 chunks
        CP16(vb + sw4(r, ch), g_v + (((size_t)b*C_ + r)*N_ + j0)/8 + ch);
    }
}

__global__ __launch_bounds__(512, 1) void attn_ws_kernel(
    const float* __restrict__ x,
    const float* __restrict__ Wo, const float* __restrict__ bo,
    float* __restrict__ y)
{
    extern __shared__ char smc[];
    const int tid  = threadIdx.x;
    const int lane = tid & 31;
    const int wid  = tid >> 5;
    const bool is_s = (wid >= 8);
    const int s    = wid & 7;
    const int row0 = s * 16;
    const int b    = blockIdx.y;
    const int q0   = blockIdx.x * 128;
    const uint32_t smb = smem_u32(smc);

    stage_tile_n<512>(smc + AT_QHI, g_qt_hi + ((size_t)b*N_ + q0)*16, 16, tid);
    stage_tile_n<512>(smc + AT_QLO, g_qt_lo + ((size_t)b*N_ + q0)*16, 16, tid);
    stage_kv32(smb, b, 0, tid); CP_COMMIT();
    stage_kv32(smb, b, 1, tid); CP_COMMIT();

    const int ar = (lane & 7) + (((lane >> 3) & 1) << 3);
    const int ac = lane >> 4;
    const int br = (lane & 7) + ((lane >> 4) << 3);
    const int bc = (lane >> 3) & 1;
    const int rg = lane >> 2;        // row group 0..7

    // S-warp state
    float m0 = -1e30f, m1 = -1e30f, ls0 = 0.f, ls1 = 0.f;
    // O-warp state
    float O[16][4];
    #pragma unroll
    for (int t = 0; t < 16; t++)
        #pragma unroll
        for (int k = 0; k < 4; k++) O[t][k] = 0.f;

    for (int jt = 0; jt <= NCH; jt++) {
        CP_WAIT1();
        __syncthreads();
        if (jt + 2 < NCH) stage_kv32(smb, b, jt + 2, tid);
        CP_COMMIT();

        if (is_s) {
            if (jt < NCH) {
                // ---- GEMM1: S[16 x 32] (3-term fp16 split) ----
                const uint32_t kb = smb + KR + (uint32_t)(jt % 3) * KBUF_SZ;
                float S[4][4];
                #pragma unroll
                for (int t = 0; t < 4; t++)
                    #pragma unroll
                    for (int k = 0; k < 4; k++) S[t][k] = 0.f;
                #pragma unroll
                for (int J = 0; J < 8; J++) {
                    uint32_t aqh[4], aql[4];
                    ldsm_x4(aqh, smb + AT_QHI + sw_off(row0 + ar, 2*J + ac));
                    ldsm_x4(aql, smb + AT_QLO + sw_off(row0 + ar, 2*J + ac));
                    #pragma unroll
                    for (int nt = 0; nt < 2; nt++) {
                        uint32_t bh[4], bl[4];
                        ldsm_x4(bh, kb +        sw_off(nt*16 + br, 2*J + bc));
                        ldsm_x4(bl, kb + 8192 + sw_off(nt*16 + br, 2*J + bc));
                        mma16816(S[2*nt],   aqh, bh);
                        mma16816(S[2*nt+1], aqh, bh + 2);
                        mma16816(S[2*nt],   aqh, bl);
                        mma16816(S[2*nt+1], aqh, bl + 2);
                        mma16816(S[2*nt],   aql, bh);
                        mma16816(S[2*nt+1], aql, bh + 2);
                    }
                }
                // ---- online softmax ----
                float cm0 = fmaxf(fmaxf(S[0][0], S[0][1]), fmaxf(S[1][0], S[1][1]));
                float cm1 = fmaxf(fmaxf(S[0][2], S[0][3]), fmaxf(S[1][2], S[1][3]));
                cm0 = fmaxf(cm0, fmaxf(fmaxf(S[2][0], S[2][1]), fmaxf(S[3][0], S[3][1])));
                cm1 = fmaxf(cm1, fmaxf(fmaxf(S[2][2], S[2][3]), fmaxf(S[3][2], S[3][3])));
                cm0 = fmaxf(cm0, __shfl_xor_sync(0xffffffffu, cm0, 1));
                cm0 = fmaxf(cm0, __shfl_xor_sync(0xffffffffu, cm0, 2));
                cm1 = fmaxf(cm1, __shfl_xor_sync(0xffffffffu, cm1, 1));
                cm1 = fmaxf(cm1, __shfl_xor_sync(0xffffffffu, cm1, 2));
                const float m0n = fmaxf(m0, cm0);
                const float m1n = fmaxf(m1, cm1);
                const float a0 = __expf(m0 - m0n);
                const float a1 = __expf(m1 - m1n);
                m0 = m0n; m1 = m1n;
                ls0 *= a0; ls1 *= a1;

                uint32_t pf[2][4];
                #pragma unroll
                for (int nt = 0; nt < 4; nt++) {
                    float p0 = __expf(S[nt][0] - m0);
                    float p1 = __expf(S[nt][1] - m0);
                    float p2 = __expf(S[nt][2] - m1);
                    float p3 = __expf(S[nt][3] - m1);
                    ls0 += p0 + p1;
                    ls1 += p2 + p3;
                    pf[nt >> 1][(nt & 1)*2]     = packh(p0, p1);
                    pf[nt >> 1][(nt & 1)*2 + 1] = packh(p2, p3);
                }
                // ---- export alpha + P fragments ----
                const uint32_t bsel = (uint32_t)(jt & 1);
                if ((lane & 3) == 0) {
                    float* al = (float*)(smc + AL + bsel*512) + s*16;
                    al[rg]     = a0;
                    al[rg + 8] = a1;
                }
                uint32_t pdst = (uint32_t)(PB + bsel*PBUF_SZ + s*1024 + lane*16);
                *(uint4*)(smc + pdst)       = make_uint4(pf[0][0], pf[0][1], pf[0][2], pf[0][3]);
                *(uint4*)(smc + pdst + 512) = make_uint4(pf[1][0], pf[1][1], pf[1][2], pf[1][3]);
            }
        } else {
            if (jt >= 1) {
                const int c = jt - 1;
                const uint32_t bsel = (uint32_t)(c & 1);
                const float* al = (const float*)(smc + AL + bsel*512) + s*16;
                const float a0 = al[rg];
                const float a1 = al[rg + 8];
                #pragma unroll
                for (int ct = 0; ct < 16; ct++) {
                    O[ct][0] *= a0; O[ct][1] *= a0;
                    O[ct][2] *= a1; O[ct][3] *= a1;
                }
                const uint32_t vb = smb + VR + (uint32_t)(c % 4) * VBUF_SZ;
                const uint32_t psrc = (uint32_t)(PB + bsel*PBUF_SZ + s*1024 + lane*16);
                #pragma unroll
                for (int J = 0; J < 2; J++) {
                    uint4 pv = *(uint4*)(smc + psrc + J*512);
                    uint32_t pf[4] = { pv.x, pv.y, pv.z, pv.w };
                    #pragma unroll
                    for (int ct = 0; ct < 8; ct++) {
                        uint32_t vf[4];
                        ldsm_x4(vf, vb + sw4(ct*16 + br, J*2 + bc));
                        mma16816(O[2*ct],   pf, vf);
                        mma16816(O[2*ct+1], pf, vf + 2);
                    }
                }
            }
        }
    }

    // ---- S warps: reduce + export final row sums ----
    if (is_s) {
        ls0 += __shfl_xor_sync(0xffffffffu, ls0, 1);
        ls0 += __shfl_xor_sync(0xffffffffu, ls0, 2);
        ls1 += __shfl_xor_sync(0xffffffffu, ls1, 1);
        ls1 += __shfl_xor_sync(0xffffffffu, ls1, 2);
        if ((lane & 3) == 0) {
            float* lp = (float*)(smc + LS) + s*16;
            lp[rg]     = ls0;
            lp[rg + 8] = ls1;
        }
    }
    __syncthreads();

    // O warps load inv BEFORE the ys overlay clobbers LS
    float inv0 = 0.f, inv1 = 0.f;
    if (!is_s) {
        const float* lp = (const float*)(smc + LS) + s*16;
        inv0 = 1.f / lp[rg];
        inv1 = 1.f / lp[rg + 8];
    }
    stage_half512(smc + EP_WO, Wo, 128, tid);   // Wo -> single fp16
    __syncthreads();

    if (!is_s) {
        // pack normalized O into single-fp16 A-fragments
        uint32_t af[8][4];
        #pragma unroll
        for (int J = 0; J < 8; J++) {
            af[J][0] = packh(O[2*J][0]*inv0,   O[2*J][1]*inv0);
            af[J][1] = packh(O[2*J][2]*inv1,   O[2*J][3]*inv1);
            af[J][2] = packh(O[2*J+1][0]*inv0, O[2*J+1][1]*inv0);
            af[J][3] = packh(O[2*J+1][2]*inv1, O[2*J+1][3]*inv1);
        }
        // Y[16n x 128o] = af * Wo^T
        float Y[16][4];
        #pragma unroll
        for (int t = 0; t < 16; t++)
            #pragma unroll
            for (int k = 0; k < 4; k++) Y[t][k] = 0.f;
        #pragma unroll
        for (int J = 0; J < 8; J++) {
            #pragma unroll
            for (int ot = 0; ot < 8; ot++) {
                uint32_t wf[4];
                ldsm_x4(wf, smb + EP_WO + sw_off(ot*16 + br, 2*J + bc));
                mma16816(Y[2*ot],   af[J], wf);
                mma16816(Y[2*ot+1], af[J], wf + 2);
            }
        }
        // scatter to transpose buffer ys[o][n]
        float* ys = (float*)(smc + EP_YS);
        const int o2 = (lane & 3) * 2;
        #pragma unroll
        for (int ct = 0; ct < 16; ct++) {
            int o = ct*8 + o2;
            ys[(o  )*YS_STR + row0 + rg    ] = Y[ct][0];
            ys[(o+1)*YS_STR + row0 + rg    ] = Y[ct][1];
            ys[(o  )*YS_STR + row0 + rg + 8] = Y[ct][2];
            ys[(o+1)*YS_STR + row0 + rg + 8] = Y[ct][3];
        }
    }
    __syncthreads();

    // coalesced store (all 512 threads): y = ys + bo + x
    float* ys = (float*)(smc + EP_YS);
    #pragma unroll
    for (int it = 0; it < 8; it++) {
        int i = tid + it * 512;
        int o = i >> 5, nq = (i & 31) * 4;
        float4 yv = *(float4*)(ys + o*YS_STR + nq);
        const float bb = bo[o];
        size_t gidx = ((size_t)b*C_ + o)*N_ + q0 + nq;
        float4 xv = *(const float4*)(x + gidx);
        *(float4*)(y + gidx) = make_float4(yv.x + bb + xv.x, yv.y + bb + xv.y,
                                           yv.z + bb + xv.z, yv.w + bb + xv.w);
    }
}

// ---------------------------------------------------------------------------
extern "C" void kernel_launch(void* const* d_in, const int* in_sizes, int n_in,
                              void* d_out, int out_size)
{
    const float* x  = (const float*)d_in[0];
    const float* Wq = (const float*)d_in[1];
    const float* bq = (const float*)d_in[2];
    const float* Wk = (const float*)d_in[3];
    const float* bk = (const float*)d_in[4];
    const float* Wv = (const float*)d_in[5];
    const float* bv = (const float*)d_in[6];
    const float* Wo = (const float*)d_in[7];
    const float* bo = (const float*)d_in[8];
    float* y = (float*)d_out;

    cudaFuncSetAttribute(proj_qkv_mma,   cudaFuncAttributeMaxDynamicSharedMemorySize, PJ_TOTAL);
    cudaFuncSetAttribute(attn_ws_kernel, cudaFuncAttributeMaxDynamicSharedMemorySize, AT_TOTAL);

    proj_qkv_mma<<<dim3(32, B_), 512, PJ_TOTAL>>>(x, Wq, bq, Wk, bk, Wv, bv);
    attn_ws_kernel<<<dim3(32, B_), 512, AT_TOTAL>>>(x, Wo, bo, y);
}

// round 17
// speedup vs baseline: 1.4220x; 1.4220x over previous
#include <cuda_runtime.h>
#include <cuda_fp16.h>
#include <cstdint>

#define B_ 4
#define C_ 128
#define N_ 4096

// ---------------------------------------------------------------------------
// Scratch (static device globals, 16B aligned via uint4). All fp16 payloads.
// ---------------------------------------------------------------------------
__device__ uint4 g_qt_hi[(size_t)B_*N_*C_/8];   // fp16 [b][n][c]
__device__ uint4 g_qt_lo[(size_t)B_*N_*C_/8];
__device__ uint4 g_kt_hi[(size_t)B_*N_*C_/8];   // fp16 [b][n][c]
__device__ uint4 g_kt_lo[(size_t)B_*N_*C_/8];
__device__ uint4 g_v   [(size_t)B_*N_*C_/8];    // fp16 [b][c][n]  (single)

// ---------------------------------------------------------------------------
// Portable tensor-core helpers (plain sm_103 target)
// ---------------------------------------------------------------------------
__device__ __forceinline__ uint32_t smem_u32(const void* p) {
    uint32_t a;
    asm("{ .reg .u64 t; cvta.to.shared.u64 t, %1; cvt.u32.u64 %0, t; }"
        : "=r"(a) : "l"(p));
    return a;
}
__device__ __forceinline__ void ldsm_x4(uint32_t* r, uint32_t addr) {
    asm volatile("ldmatrix.sync.aligned.m8n8.x4.shared.b16 {%0,%1,%2,%3}, [%4];"
                 : "=r"(r[0]), "=r"(r[1]), "=r"(r[2]), "=r"(r[3]) : "r"(addr));
}
__device__ __forceinline__ void ldsm_x4_t(uint32_t* r, uint32_t addr) {
    asm volatile("ldmatrix.sync.aligned.m8n8.x4.trans.shared.b16 {%0,%1,%2,%3}, [%4];"
                 : "=r"(r[0]), "=r"(r[1]), "=r"(r[2]), "=r"(r[3]) : "r"(addr));
}
__device__ __forceinline__ void mma16816(float* c, const uint32_t* a, const uint32_t* b) {
    asm volatile(
        "mma.sync.aligned.m16n8k16.row.col.f32.f16.f16.f32 "
        "{%0,%1,%2,%3}, {%4,%5,%6,%7}, {%8,%9}, {%0,%1,%2,%3};"
        : "+f"(c[0]), "+f"(c[1]), "+f"(c[2]), "+f"(c[3])
        : "r"(a[0]), "r"(a[1]), "r"(a[2]), "r"(a[3]), "r"(b[0]), "r"(b[1]));
}
__device__ __forceinline__ uint32_t packh(float a, float b) {   // low16 = a
    __half2 h = __floats2half2_rn(a, b);
    return *reinterpret_cast<uint32_t*>(&h);
}
__device__ __forceinline__ void split2h(float a, float b, uint32_t& h, uint32_t& l) {
    __half2 hh = __floats2half2_rn(a, b);
    float2  hf = __half22float2(hh);
    __half2 ll = __floats2half2_rn(a - hf.x, b - hf.y);
    h = *reinterpret_cast<uint32_t*>(&hh);
    l = *reinterpret_cast<uint32_t*>(&ll);
}

// Swizzled tiles: 256B rows (16 x 16B chunks) and 128B rows (8 chunks)
__device__ __forceinline__ uint32_t sw_off(int r, int ch) {
    return (uint32_t)(r * 256 + ((ch ^ (r & 7)) << 4));
}
__device__ __forceinline__ uint32_t sw8(int r, int ch) {
    return (uint32_t)(r * 128 + ((ch ^ (r & 7)) << 4));
}
// Copy 128x(16 uint4) fp16 tile into swizzled SMEM (256 threads).
__device__ __forceinline__ void stage_tile(char* dst, const uint4* __restrict__ g,
                                           int rs, int tid) {
    #pragma unroll
    for (int it = 0; it < 8; it++) {
        int i = tid + it * 256;
        int r = i >> 4, ch = i & 15;
        uint4 v = g[(size_t)r * rs + ch];
        *(uint4*)(dst + sw_off(r, ch)) = v;
    }
}
// fp32 gmem tile (128x128, stride rs floats) -> swizzled fp16 hi/lo (512 thr)
__device__ __forceinline__ void stage_split512(char* hi, char* lo,
                                               const float* __restrict__ g,
                                               size_t rs, int tid) {
    #pragma unroll
    for (int it = 0; it < 4; it++) {
        int i = tid + it * 512;
        int r = i >> 4, ch = i & 15;
        const float* p = g + (size_t)r * rs + ch * 8;
        float4 f0 = *(const float4*)p;
        float4 f1 = *(const float4*)(p + 4);
        uint32_t h0,l0,h1,l1,h2,l2,h3,l3;
        split2h(f0.x, f0.y, h0, l0);
        split2h(f0.z, f0.w, h1, l1);
        split2h(f1.x, f1.y, h2, l2);
        split2h(f1.z, f1.w, h3, l3);
        uint32_t off = sw_off(r, ch);
        *(uint4*)(hi + off) = make_uint4(h0, h1, h2, h3);
        *(uint4*)(lo + off) = make_uint4(l0, l1, l2, l3);
    }
}
// fp32 gmem tile (128x128, stride rs floats) -> swizzled SINGLE fp16 (256 thr)
__device__ __forceinline__ void stage_half(char* dst, const float* __restrict__ g,
                                           size_t rs, int tid) {
    #pragma unroll
    for (int it = 0; it < 8; it++) {
        int i = tid + it * 256;
        int r = i >> 4, ch = i & 15;
        const float* p = g + (size_t)r * rs + ch * 8;
        float4 f0 = *(const float4*)p;
        float4 f1 = *(const float4*)(p + 4);
        *(uint4*)(dst + sw_off(r, ch)) =
            make_uint4(packh(f0.x, f0.y), packh(f0.z, f0.w),
                       packh(f1.x, f1.y), packh(f1.z, f1.w));
    }
}

#define CP16(s, g) asm volatile("cp.async.cg.shared.global [%0], [%1], 16;" \
                                :: "r"(s), "l"(g) : "memory")
#define CP_COMMIT() asm volatile("cp.async.commit_group;" ::: "memory")
#define CP_WAIT1()  asm volatile("cp.async.wait_group 1;" ::: "memory")
#define CP_WAIT0()  asm volatile("cp.async.wait_group 0;" ::: "memory")

// ---------------------------------------------------------------------------
// Kernel 1: merged QKV projection, 512 threads / 16 warps.
// Each warp: one 16-row strip x HALF the output dim (halved latency chain).
// ---------------------------------------------------------------------------
#define PJ_WHI 0
#define PJ_WLO 32768
#define PJ_XHI 65536
#define PJ_XLO 98304
#define PJ_TOTAL 131072

__global__ __launch_bounds__(512, 1) void proj_qkv_mma(
    const float* __restrict__ x,
    const float* __restrict__ Wq, const float* __restrict__ bq,
    const float* __restrict__ Wk, const float* __restrict__ bk,
    const float* __restrict__ Wv, const float* __restrict__ bv)
{
    extern __shared__ char smc[];
    const int tid = threadIdx.x, lane = tid & 31, wid = tid >> 5;
    const int nt0 = blockIdx.x, b = blockIdx.y;
    const int n0 = nt0 * 128;
    const uint32_t smb = smem_u32(smc);

    stage_split512(smc + PJ_XHI, smc + PJ_XLO, x + (size_t)b*C_*N_ + n0, N_, tid);

    for (int which = 0; which < 3; which++) {
        const float* W    = (which == 0) ? Wq : (which == 1) ? Wk : Wv;
        const float* bias = (which == 0) ? bq : (which == 1) ? bk : bv;
        if (which) __syncthreads();
        stage_split512(smc + PJ_WHI, smc + PJ_WLO, W, 128, tid);
        __syncthreads();

        float acc[8][4];
        #pragma unroll
        for (int i = 0; i < 8; i++)
            #pragma unroll
            for (int k = 0; k < 4; k++) acc[i][k] = 0.f;

        if (which < 2) {
            // C[n][o]: A = x^T (trans ldsm), B = W.  strip sn, o-half oh.
            const int sn = wid >> 1, oh = wid & 1;
            const int ta_r = (lane & 7) + ((lane >> 4) << 3);
            const int ta_c = (lane >> 3) & 1;
            const int br = (lane & 7) + ((lane >> 4) << 3);
            const int bc = (lane >> 3) & 1;
            const int nch = sn * 2;
            #pragma unroll
            for (int J = 0; J < 8; J++) {
                uint32_t axh[4], axl[4];
                ldsm_x4_t(axh, smb + PJ_XHI + sw_off(J*16 + ta_r, nch + ta_c));
                ldsm_x4_t(axl, smb + PJ_XLO + sw_off(J*16 + ta_r, nch + ta_c));
                #pragma unroll
                for (int ot = 0; ot < 4; ot++) {
                    uint32_t bwh[4], bwl[4];
                    ldsm_x4(bwh, smb + PJ_WHI + sw_off(oh*64 + ot*16 + br, 2*J + bc));
                    ldsm_x4(bwl, smb + PJ_WLO + sw_off(oh*64 + ot*16 + br, 2*J + bc));
                    mma16816(acc[2*ot],   axh, bwh);
                    mma16816(acc[2*ot+1], axh, bwh + 2);
                    mma16816(acc[2*ot],   axh, bwl);
                    mma16816(acc[2*ot+1], axh, bwl + 2);
                    mma16816(acc[2*ot],   axl, bwh);
                    mma16816(acc[2*ot+1], axl, bwh + 2);
                }
            }
            uint32_t* ohp = (uint32_t*)((which == 0) ? g_qt_hi : g_kt_hi);
            uint32_t* olp = (uint32_t*)((which == 0) ? g_qt_lo : g_kt_lo);
            const int n_g = n0 + sn*16 + (lane >> 2);
            #pragma unroll
            for (int ct = 0; ct < 8; ct++) {
                int o = oh*64 + ct*8 + (lane & 3)*2;
                float b0 = bias[o], b1 = bias[o+1];
                uint32_t h, l;
                size_t idx = ((size_t)b*N_ + n_g)*64 + oh*32 + ct*4 + (lane & 3);
                split2h(acc[ct][0] + b0, acc[ct][1] + b1, h, l);
                ohp[idx] = h; olp[idx] = l;
                split2h(acc[ct][2] + b0, acc[ct][3] + b1, h, l);
                ohp[idx + 8*64] = h; olp[idx + 8*64] = l;
            }
        } else {
            // C[o][n]: A = W, B = x^T (trans ldsm).  o-strip so, n-half nh.
            const int so = wid >> 1, nh = wid & 1;
            const int ar = (lane & 7) + (((lane >> 3) & 1) << 3);
            const int ac = lane >> 4;
            const int tb_r = (lane & 7) + (((lane >> 3) & 1) << 3);
            const int tb_c = lane >> 4;
            #pragma unroll
            for (int J = 0; J < 8; J++) {
                uint32_t awh[4], awl[4];
                ldsm_x4(awh, smb + PJ_WHI + sw_off(so*16 + ar, 2*J + ac));
                ldsm_x4(awl, smb + PJ_WLO + sw_off(so*16 + ar, 2*J + ac));
                #pragma unroll
                for (int nt = 0; nt < 4; nt++) {
                    uint32_t bxh[4], bxl[4];
                    ldsm_x4_t(bxh, smb + PJ_XHI + sw_off(J*16 + tb_r, nh*8 + nt*2 + tb_c));
                    ldsm_x4_t(bxl, smb + PJ_XLO + sw_off(J*16 + tb_r, nh*8 + nt*2 + tb_c));
                    mma16816(acc[2*nt],   awh, bxh);
                    mma16816(acc[2*nt+1], awh, bxh + 2);
                    mma16816(acc[2*nt],   awh, bxl);
                    mma16816(acc[2*nt+1], awh, bxl + 2);
                    mma16816(acc[2*nt],   awl, bxh);
                    mma16816(acc[2*nt+1], awl, bxh + 2);
                }
            }
            uint32_t* ov = (uint32_t*)g_v;
            const int o_g = so*16 + (lane >> 2);
            const float b0 = bias[o_g], b1 = bias[o_g + 8];
            #pragma unroll
            for (int nt = 0; nt < 8; nt++) {
                size_t idx = (((size_t)b*C_ + o_g)*N_ + n0)/2 + nh*32 + nt*4 + (lane & 3);
                ov[idx]            = packh(acc[nt][0] + b0, acc[nt][1] + b0);
                ov[idx + 8*(N_/2)] = packh(acc[nt][2] + b1, acc[nt][3] + b1);
            }
        }
    }
}

// ---------------------------------------------------------------------------
// Kernel 2: fused-interleave flash attention + fused output projection.
// (R15 structure unchanged — best measured attn at 183.9us.)
// ---------------------------------------------------------------------------
#define AT_QHI 0
#define AT_QLO 32768
#define AT_BUF 65536
#define BUF_SZ 49152
#define BK_HI 0
#define BK_LO 16384
#define BV    32768
#define AT_TOTAL (AT_BUF + 3*BUF_SZ)   // 212992
#define EP_WO 65536
#define EP_YS 98304
#define YS_STR 132

__device__ __forceinline__ void stage_kv_async(uint32_t sbase, int b, int j0, int tid) {
    const uint4* kh = g_kt_hi + ((size_t)b*N_ + j0)*16;
    const uint4* kl = g_kt_lo + ((size_t)b*N_ + j0)*16;
    #pragma unroll
    for (int t = 0; t < 4; t++) {
        int i = tid + t*256;
        int r = i >> 4, ch = i & 15;
        uint32_t so = sw_off(r, ch);
        CP16(sbase + BK_HI + so, kh + (size_t)r*16 + ch);
        CP16(sbase + BK_LO + so, kl + (size_t)r*16 + ch);
    }
    const uint4* v = g_v + ((size_t)b*C_*N_ + j0)/8;
    #pragma unroll
    for (int t = 0; t < 4; t++) {
        int i = tid + t*256;
        int r = i >> 3, ch = i & 7;
        CP16(sbase + BV + sw8(r, ch), v + (size_t)r*(N_/8) + ch);
    }
}

__device__ __forceinline__ void attn_gemm1(float (&S)[8][4], uint32_t smb,
                                           uint32_t bufb, int row0,
                                           int ar, int ac, int br, int bc) {
    #pragma unroll
    for (int t = 0; t < 8; t++)
        #pragma unroll
        for (int k = 0; k < 4; k++) S[t][k] = 0.f;
    #pragma unroll
    for (int J = 0; J < 8; J++) {
        uint32_t aqh[4], aql[4];
        ldsm_x4(aqh, smb + AT_QHI + sw_off(row0 + ar, 2*J + ac));
        ldsm_x4(aql, smb + AT_QLO + sw_off(row0 + ar, 2*J + ac));
        #pragma unroll
        for (int nt = 0; nt < 4; nt++) {
            uint32_t bh[4], bl[4];
            ldsm_x4(bh, bufb + BK_HI + sw_off(nt*16 + br, 2*J + bc));
            ldsm_x4(bl, bufb + BK_LO + sw_off(nt*16 + br, 2*J + bc));
            mma16816(S[2*nt],   aqh, bh);
            mma16816(S[2*nt+1], aqh, bh + 2);
            mma16816(S[2*nt],   aqh, bl);
            mma16816(S[2*nt+1], aqh, bl + 2);
            mma16816(S[2*nt],   aql, bh);
            mma16816(S[2*nt+1], aql, bh + 2);
        }
    }
}

__device__ __forceinline__ void attn_body(int jt, uint32_t smb, int b, int tid,
    int row0, int ar, int ac, int br, int bc,
    float (&Sr)[8][4], float (&Sw)[8][4], float (&O)[16][4],
    float& m0, float& m1, float& lsum0, float& lsum1)
{
    CP_WAIT0();
    __syncthreads();
    if (jt + 2 < 64)
        stage_kv_async(smb + AT_BUF + (uint32_t)((jt+2)%3)*BUF_SZ, b, (jt+2)*64, tid);
    CP_COMMIT();

    // ---- row-max reduce on Sr ----
    float cm0 = -1e30f, cm1 = -1e30f;
    #pragma unroll
    for (int t = 0; t < 8; t++) {
        cm0 = fmaxf(cm0, fmaxf(Sr[t][0], Sr[t][1]));
        cm1 = fmaxf(cm1, fmaxf(Sr[t][2], Sr[t][3]));
    }
    cm0 = fmaxf(cm0, __shfl_xor_sync(0xffffffffu, cm0, 1));
    cm0 = fmaxf(cm0, __shfl_xor_sync(0xffffffffu, cm0, 2));
    cm1 = fmaxf(cm1, __shfl_xor_sync(0xffffffffu, cm1, 1));
    cm1 = fmaxf(cm1, __shfl_xor_sync(0xffffffffu, cm1, 2));
    const float m0n = fmaxf(m0, cm0);
    const float m1n = fmaxf(m1, cm1);
    const float a0 = __expf(m0 - m0n);
    const float a1 = __expf(m1 - m1n);
    m0 = m0n; m1 = m1n;
    lsum0 *= a0; lsum1 *= a1;

    // zero Sw (next chunk accumulator)
    #pragma unroll
    for (int t = 0; t < 8; t++)
        #pragma unroll
        for (int k = 0; k < 4; k++) Sw[t][k] = 0.f;

    // ---- fused loop: GEMM1(jt+1) k-step J + softmax slice nt=J ----
    const uint32_t bufn = smb + AT_BUF + (uint32_t)(((jt+1)%3))*BUF_SZ;
    #pragma unroll
    for (int J = 0; J < 8; J++) {
        uint32_t aqh[4], aql[4];
        ldsm_x4(aqh, smb + AT_QHI + sw_off(row0 + ar, 2*J + ac));
        ldsm_x4(aql, smb + AT_QLO + sw_off(row0 + ar, 2*J + ac));
        #pragma unroll
        for (int nt = 0; nt < 4; nt++) {
            uint32_t bh[4], bl[4];
            ldsm_x4(bh, bufn + BK_HI + sw_off(nt*16 + br, 2*J + bc));
            ldsm_x4(bl, bufn + BK_LO + sw_off(nt*16 + br, 2*J + bc));
            mma16816(Sw[2*nt],   aqh, bh);
            mma16816(Sw[2*nt+1], aqh, bh + 2);
            mma16816(Sw[2*nt],   aqh, bl);
            mma16816(Sw[2*nt+1], aqh, bl + 2);
            mma16816(Sw[2*nt],   aql, bh);
            mma16816(Sw[2*nt+1], aql, bh + 2);
        }
        {
            float p0 = __expf(Sr[J][0] - m0);
            float p1 = __expf(Sr[J][1] - m0);
            float p2 = __expf(Sr[J][2] - m1);
            float p3 = __expf(Sr[J][3] - m1);
            lsum0 += p0 + p1;
            lsum1 += p2 + p3;
            Sr[J >> 1][(J & 1)*2]     = __uint_as_float(packh(p0, p1));
            Sr[J >> 1][(J & 1)*2 + 1] = __uint_as_float(packh(p2, p3));
            O[2*J][0]   *= a0; O[2*J][1]   *= a0;
            O[2*J][2]   *= a1; O[2*J][3]   *= a1;
            O[2*J+1][0] *= a0; O[2*J+1][1] *= a0;
            O[2*J+1][2] *= a1; O[2*J+1][3] *= a1;
        }
    }

    // ---- GEMM2: O += P V^T (chunk jt); P bits live in Sr[0..3] ----
    const uint32_t bufc = smb + AT_BUF + (uint32_t)(jt % 3) * BUF_SZ;
    #pragma unroll
    for (int J = 0; J < 4; J++) {
        uint32_t pf[4] = { __float_as_uint(Sr[J][0]), __float_as_uint(Sr[J][1]),
                           __float_as_uint(Sr[J][2]), __float_as_uint(Sr[J][3]) };
        #pragma unroll
        for (int ct = 0; ct < 8; ct++) {
            uint32_t vf[4];
            ldsm_x4(vf, bufc + BV + sw8(ct*16 + br, 2*J + bc));
            mma16816(O[2*ct],   pf, vf);
            mma16816(O[2*ct+1], pf, vf + 2);
        }
    }
}

__global__ __launch_bounds__(256, 1) void attn_fused_kernel(
    const float* __restrict__ x,
    const float* __restrict__ Wo, const float* __restrict__ bo,
    float* __restrict__ y)
{
    extern __shared__ char smc[];
    const int tid  = threadIdx.x;
    const int lane = tid & 31;
    const int wid  = tid >> 5;
    const int b    = blockIdx.y;
    const int q0   = blockIdx.x * 128;
    const uint32_t smb = smem_u32(smc);

    stage_tile(smc + AT_QHI, g_qt_hi + ((size_t)b*N_ + q0)*16, 16, tid);
    stage_tile(smc + AT_QLO, g_qt_lo + ((size_t)b*N_ + q0)*16, 16, tid);
    stage_kv_async(smb + AT_BUF + 0*BUF_SZ, b, 0, tid);
    CP_COMMIT();
    stage_kv_async(smb + AT_BUF + 1*BUF_SZ, b, 64, tid);
    CP_COMMIT();

    const int row0 = wid * 16;
    const int ar = (lane & 7) + (((lane >> 3) & 1) << 3);
    const int ac = lane >> 4;
    const int br = (lane & 7) + ((lane >> 4) << 3);
    const int bc = (lane >> 3) & 1;

    float O[16][4];
    #pragma unroll
    for (int t = 0; t < 16; t++)
        #pragma unroll
        for (int k = 0; k < 4; k++) O[t][k] = 0.f;
    float m0 = -1e30f, m1 = -1e30f;
    float lsum0 = 0.f, lsum1 = 0.f;

    float Sa[8][4], Sb[8][4];
    CP_WAIT1();
    __syncthreads();
    attn_gemm1(Sa, smb, smb + AT_BUF + 0*BUF_SZ, row0, ar, ac, br, bc);

    for (int jt = 0; jt < 64; jt += 2) {
        attn_body(jt,     smb, b, tid, row0, ar, ac, br, bc, Sa, Sb, O, m0, m1, lsum0, lsum1);
        attn_body(jt + 1, smb, b, tid, row0, ar, ac, br, bc, Sb, Sa, O, m0, m1, lsum0, lsum1);
    }

    lsum0 += __shfl_xor_sync(0xffffffffu, lsum0, 1);
    lsum0 += __shfl_xor_sync(0xffffffffu, lsum0, 2);
    lsum1 += __shfl_xor_sync(0xffffffffu, lsum1, 1);
    lsum1 += __shfl_xor_sync(0xffffffffu, lsum1, 2);
    const float inv0 = 1.f / lsum0;
    const float inv1 = 1.f / lsum1;

    // ============== fused output projection epilogue ==============
    __syncthreads();
    stage_half(smc + EP_WO, Wo, 128, tid);
    __syncthreads();

    uint32_t af[8][4];
    #pragma unroll
    for (int J = 0; J < 8; J++) {
        af[J][0] = packh(O[2*J][0]*inv0,   O[2*J][1]*inv0);
        af[J][1] = packh(O[2*J][2]*inv1,   O[2*J][3]*inv1);
        af[J][2] = packh(O[2*J+1][0]*inv0, O[2*J+1][1]*inv0);
        af[J][3] = packh(O[2*J+1][2]*inv1, O[2*J+1][3]*inv1);
    }

    float Y[16][4];
    #pragma unroll
    for (int t = 0; t < 16; t++)
        #pragma unroll
        for (int k = 0; k < 4; k++) Y[t][k] = 0.f;
    #pragma unroll
    for (int J = 0; J < 8; J++) {
        #pragma unroll
        for (int ot = 0; ot < 8; ot++) {
            uint32_t wf[4];
            ldsm_x4(wf, smb + EP_WO + sw_off(ot*16 + br, 2*J + bc));
            mma16816(Y[2*ot],   af[J], wf);
            mma16816(Y[2*ot+1], af[J], wf + 2);
        }
    }

    float* ys = (float*)(smc + EP_YS);
    {
        const int r  = lane >> 2;
        const int o2 = (lane & 3) * 2;
        #pragma unroll
        for (int ct = 0; ct < 16; ct++) {
            int o = ct*8 + o2;
            ys[(o  )*YS_STR + row0 + r    ] = Y[ct][0];
            ys[(o+1)*YS_STR + row0 + r    ] = Y[ct][1];
            ys[(o  )*YS_STR + row0 + r + 8] = Y[ct][2];
            ys[(o+1)*YS_STR + row0 + r + 8] = Y[ct][3];
        }
    }
    __syncthreads();

    #pragma unroll
    for (int it = 0; it < 16; it++) {
        int i = tid + it * 256;
        int o = i >> 5, nq = (i & 31) * 4;
        float4 yv = *(float4*)(ys + o*YS_STR + nq);
        const float bb = bo[o];
        size_t gidx = ((size_t)b*C_ + o)*N_ + q0 + nq;
        float4 xv = *(const float4*)(x + gidx);
        *(float4*)(y + gidx) = make_float4(yv.x + bb + xv.x, yv.y + bb + xv.y,
                                           yv.z + bb + xv.z, yv.w + bb + xv.w);
    }
}

// ---------------------------------------------------------------------------
extern "C" void kernel_launch(void* const* d_in, const int* in_sizes, int n_in,
                              void* d_out, int out_size)
{
    const float* x  = (const float*)d_in[0];
    const float* Wq = (const float*)d_in[1];
    const float* bq = (const float*)d_in[2];
    const float* Wk = (const float*)d_in[3];
    const float* bk = (const float*)d_in[4];
    const float* Wv = (const float*)d_in[5];
    const float* bv = (const float*)d_in[6];
    const float* Wo = (const float*)d_in[7];
    const float* bo = (const float*)d_in[8];
    float* y = (float*)d_out;

    cudaFuncSetAttribute(proj_qkv_mma,      cudaFuncAttributeMaxDynamicSharedMemorySize, PJ_TOTAL);
    cudaFuncSetAttribute(attn_fused_kernel, cudaFuncAttributeMaxDynamicSharedMemorySize, AT_TOTAL);

    proj_qkv_mma<<<dim3(32, B_), 512, PJ_TOTAL>>>(x, Wq, bq, Wk, bk, Wv, bv);
    attn_fused_kernel<<<dim3(32, B_), 256, AT_TOTAL>>>(x, Wo, bo, y);
}